// round 6
// baseline (speedup 1.0000x reference)
#include <cuda_runtime.h>
#include <math.h>

#define UNITS   512
#define ORDER   256
#define TSTEPS  1024
#define BATCH   64

#define NCTA     128
#define NTHREADS 256
#define GROUPS   8
#define CPG      16   // CTAs per group
#define BPG      8    // batches per group
#define JH       32   // h columns per CTA
#define JM       16   // m columns per CTA

#define WHK_STRIDE 516
#define WMK_STRIDE 260
#define WAT_STRIDE 260

// ---- shared memory layout (in floats) ----
#define WHK_OFF  0
#define WMK_OFF  (WHK_OFF + JH*WHK_STRIDE)     // 16512
#define WAT_OFF  (WMK_OFF + JH*WMK_STRIDE)     // 24832
#define HS_OFF   (WAT_OFF + JM*WAT_STRIDE)     // 28992  (8 x 512)
#define MS_OFF   (HS_OFF + BPG*UNITS)          // 33088  (8 x 256)
#define IK_OFF   (MS_OFF + BPG*ORDER)          // 35136
#define BTMK_OFF (IK_OFF + JH)
#define HE_OFF   (BTMK_OFF + JH)
#define BT_OFF   (HE_OFF + JH)
#define ME_OFF   (BT_OFF + JM)
#define XV_OFF   (ME_OFF + JM)
#define US_OFF   (XV_OFF + BPG)
#define HEP_OFF  (US_OFF + BPG)
#define MEP_OFF  (HEP_OFF + BPG)
#define IE_OFF   (MEP_OFF + BPG)
#define SMEM_FLOATS (IE_OFF + 4)
#define SMEM_BYTES  (SMEM_FLOATS * 4)

// ---- device scratch (no allocations allowed) ----
__device__ float d_MK2[ORDER * UNITS];                    // mk + AT@mk
__device__ float d_BTmk[UNITS];                           // BT@mk
__device__ float d_hbuf[2][BATCH * UNITS];                // double-buffered h state
__device__ float d_mbuf[2][BATCH * ORDER];                // double-buffered m state
__device__ float d_upart[(TSTEPS + 1) * BATCH * CPG];     // per-CTA partials of h.he + m.me
__device__ unsigned int d_bar_count[GROUPS];
__device__ volatile unsigned int d_bar_gen[GROUPS];

typedef unsigned long long u64;

__device__ __forceinline__ void fma2(u64 &acc, u64 a, u64 b) {
    asm("fma.rn.f32x2 %0, %1, %2, %0;" : "+l"(acc) : "l"(a), "l"(b));
}
__device__ __forceinline__ float red2(u64 v) {
    float lo, hi;
    asm("mov.b64 {%0, %1}, %2;" : "=f"(lo), "=f"(hi) : "l"(v));
    return lo + hi;
}

// ===================== setup: fold matrices, zero state, reset barriers =====================
__global__ void lmu_setup_kernel(const float* __restrict__ mk,
                                 const float* __restrict__ AT,
                                 const float* __restrict__ BT) {
    int blk = blockIdx.x, tid = threadIdx.x;
    if (blk < 512) {
        // MK2[k][j] = mk[k][j] + sum_q AT[k][q] * mk[q][j]
        int e = blk * 256 + tid;           // 0 .. 131071
        int k = e >> 9, j = e & 511;
        float acc = mk[k * UNITS + j];
        const float* atrow = AT + k * ORDER;
        #pragma unroll 4
        for (int q = 0; q < ORDER; ++q) acc += atrow[q] * mk[q * UNITS + j];
        d_MK2[e] = acc;
    } else if (blk == 512) {
        for (int j = tid; j < UNITS; j += 256) {
            float acc = 0.f;
            #pragma unroll 4
            for (int q = 0; q < ORDER; ++q) acc += BT[q] * mk[q * UNITS + j];
            d_BTmk[j] = acc;
        }
    } else if (blk <= 518) {
        int base = (blk - 513) * 256 + tid;   // 6 blocks x 256 = 1536 threads
        for (int i = base; i < BATCH * UNITS; i += 6 * 256) d_hbuf[0][i] = 0.f;
        for (int i = base; i < BATCH * ORDER; i += 6 * 256) d_mbuf[0][i] = 0.f;
    } else {
        if (tid < GROUPS) { d_bar_count[tid] = 0; d_bar_gen[tid] = 0; }
    }
}

// ===================== main persistent kernel =====================
extern __shared__ float smem[];

__global__ void __launch_bounds__(NTHREADS, 1)
lmu_main_kernel(const float* __restrict__ x,    // [64,1024,1]
                const float* __restrict__ ie,   // [1,1]
                const float* __restrict__ he,   // [512,1]
                const float* __restrict__ me,   // [256,1]
                const float* __restrict__ ik,   // [1,512]
                const float* __restrict__ hk,   // [512,512]
                const float* __restrict__ AT,   // [256,256]
                const float* __restrict__ BT,   // [1,256]
                float* __restrict__ out)        // [64,1024,512]
{
    const int tid = threadIdx.x;
    const int g   = blockIdx.x >> 4;     // group 0..7
    const int cg  = blockIdx.x & 15;     // CTA within group 0..15
    const int b0  = g * BPG;
    const int jh0 = cg * JH;
    const int jm0 = cg * JM;

    // ---- one-time: load weight slices into SMEM (transposed, padded) ----
    for (int i = tid; i < JH * UNITS; i += NTHREADS) {          // whk[j][k] = hk[k][jh0+j]
        int k = i >> 5, j = i & 31;
        smem[WHK_OFF + j * WHK_STRIDE + k] = hk[k * UNITS + jh0 + j];
    }
    for (int i = tid; i < JH * ORDER; i += NTHREADS) {          // wmk[j][k] = MK2[k][jh0+j]
        int k = i >> 5, j = i & 31;
        smem[WMK_OFF + j * WMK_STRIDE + k] = d_MK2[k * UNITS + jh0 + j];
    }
    for (int i = tid; i < JM * ORDER; i += NTHREADS) {          // wat[o][k] = AT[k][jm0+o]
        int k = i >> 4, o = i & 15;
        smem[WAT_OFF + o * WAT_STRIDE + k] = AT[k * ORDER + jm0 + o];
    }
    if (tid < JH) {
        smem[IK_OFF + tid]   = ik[jh0 + tid];
        smem[BTMK_OFF + tid] = d_BTmk[jh0 + tid];
        smem[HE_OFF + tid]   = he[jh0 + tid];
    }
    if (tid < JM) {
        smem[BT_OFF + tid] = BT[jm0 + tid];
        smem[ME_OFF + tid] = me[jm0 + tid];
    }
    if (tid == 0) smem[IE_OFF] = ie[0];
    __syncthreads();

    const int bh = tid >> 5, jj = tid & 31;   // h-job mapping (8 warps x 32 cols)
    const int bm = tid >> 4, oo = tid & 15;   // m-job mapping (threads 0..127)

    for (int t = 0; t < TSTEPS; ++t) {
        const int p = t & 1;

        // ---- stage A: fetch states from global (L2-coherent) into SMEM ----
        {
            const float4* hs = reinterpret_cast<const float4*>(d_hbuf[p] + b0 * UNITS);
            float4*       hd = reinterpret_cast<float4*>(smem + HS_OFF);
            #pragma unroll
            for (int i = tid; i < (BPG * UNITS) / 4; i += NTHREADS) hd[i] = __ldcg(hs + i);
            const float4* ms = reinterpret_cast<const float4*>(d_mbuf[p] + b0 * ORDER);
            float4*       md = reinterpret_cast<float4*>(smem + MS_OFF);
            #pragma unroll
            for (int i = tid; i < (BPG * ORDER) / 4; i += NTHREADS) md[i] = __ldcg(ms + i);
            if (tid < BPG) {
                float xv = x[(b0 + tid) * TSTEPS + t];
                float u  = xv * smem[IE_OFF];
                if (t > 0) {
                    const float* up = d_upart + ((size_t)t * BATCH + b0 + tid) * CPG;
                    #pragma unroll
                    for (int c = 0; c < CPG; ++c) u += __ldcg(up + c);
                }
                smem[XV_OFF + tid] = xv;
                smem[US_OFF + tid] = u;
            }
        }
        __syncthreads();

        // ---- stage B1: h update (every thread computes one h output) ----
        {
            const float* wrow = smem + WHK_OFF + jj * WHK_STRIDE;
            const float* hrow = smem + HS_OFF + bh * UNITS;
            u64 a0 = 0, a1 = 0, a2 = 0, a3 = 0;
            #pragma unroll 4
            for (int k = 0; k < UNITS; k += 8) {
                ulonglong2 w0 = *reinterpret_cast<const ulonglong2*>(wrow + k);
                ulonglong2 h0 = *reinterpret_cast<const ulonglong2*>(hrow + k);
                ulonglong2 w1 = *reinterpret_cast<const ulonglong2*>(wrow + k + 4);
                ulonglong2 h1 = *reinterpret_cast<const ulonglong2*>(hrow + k + 4);
                fma2(a0, w0.x, h0.x); fma2(a1, w0.y, h0.y);
                fma2(a2, w1.x, h1.x); fma2(a3, w1.y, h1.y);
            }
            const float* w2row = smem + WMK_OFF + jj * WMK_STRIDE;
            const float* mrow  = smem + MS_OFF + bh * ORDER;
            #pragma unroll 4
            for (int k = 0; k < ORDER; k += 8) {
                ulonglong2 w0 = *reinterpret_cast<const ulonglong2*>(w2row + k);
                ulonglong2 m0 = *reinterpret_cast<const ulonglong2*>(mrow + k);
                ulonglong2 w1 = *reinterpret_cast<const ulonglong2*>(w2row + k + 4);
                ulonglong2 m1 = *reinterpret_cast<const ulonglong2*>(mrow + k + 4);
                fma2(a0, w0.x, m0.x); fma2(a1, w0.y, m0.y);
                fma2(a2, w1.x, m1.x); fma2(a3, w1.y, m1.y);
            }
            float val = (red2(a0) + red2(a1)) + (red2(a2) + red2(a3));
            val += smem[XV_OFF + bh] * smem[IK_OFF + jj];
            val += smem[US_OFF + bh] * smem[BTMK_OFF + jj];
            float hv = tanhf(val);
            out[((size_t)(b0 + bh) * TSTEPS + t) * UNITS + jh0 + jj] = hv;
            __stcg(&d_hbuf[p ^ 1][(b0 + bh) * UNITS + jh0 + jj], hv);
            // deterministic warp reduction of he contribution
            float hw = smem[HE_OFF + jj] * hv;
            hw += __shfl_down_sync(0xffffffffu, hw, 16);
            hw += __shfl_down_sync(0xffffffffu, hw, 8);
            hw += __shfl_down_sync(0xffffffffu, hw, 4);
            hw += __shfl_down_sync(0xffffffffu, hw, 2);
            hw += __shfl_down_sync(0xffffffffu, hw, 1);
            if (jj == 0) smem[HEP_OFF + bh] = hw;
        }

        // ---- stage B2: m update (threads 0..127, warps 0-3, one m output each) ----
        if (tid < 128) {
            const float* arow = smem + WAT_OFF + oo * WAT_STRIDE;
            const float* mrow = smem + MS_OFF + bm * ORDER;
            u64 c0 = 0, c1 = 0, c2 = 0, c3 = 0;
            #pragma unroll 4
            for (int k = 0; k < ORDER; k += 8) {
                ulonglong2 w0 = *reinterpret_cast<const ulonglong2*>(arow + k);
                ulonglong2 m0 = *reinterpret_cast<const ulonglong2*>(mrow + k);
                ulonglong2 w1 = *reinterpret_cast<const ulonglong2*>(arow + k + 4);
                ulonglong2 m1 = *reinterpret_cast<const ulonglong2*>(mrow + k + 4);
                fma2(c0, w0.x, m0.x); fma2(c1, w0.y, m0.y);
                fma2(c2, w1.x, m1.x); fma2(c3, w1.y, m1.y);
            }
            float dot  = (red2(c0) + red2(c1)) + (red2(c2) + red2(c3));
            float mnew = mrow[jm0 + oo] + dot + smem[US_OFF + bm] * smem[BT_OFF + oo];
            __stcg(&d_mbuf[p ^ 1][(b0 + bm) * ORDER + jm0 + oo], mnew);
            // deterministic half-warp reduction of me contribution
            float mw = smem[ME_OFF + oo] * mnew;
            mw += __shfl_down_sync(0xffffffffu, mw, 8, 16);
            mw += __shfl_down_sync(0xffffffffu, mw, 4, 16);
            mw += __shfl_down_sync(0xffffffffu, mw, 2, 16);
            mw += __shfl_down_sync(0xffffffffu, mw, 1, 16);
            if (oo == 0) smem[MEP_OFF + bm] = mw;
        }
        __syncthreads();

        // ---- write u partial for step t+1 (deterministic per-CTA slot) ----
        if (tid < BPG)
            d_upart[((size_t)(t + 1) * BATCH + b0 + tid) * CPG + cg] =
                smem[HEP_OFF + tid] + smem[MEP_OFF + tid];

        __threadfence();      // all this thread's global writes visible device-wide
        __syncthreads();

        // ---- group barrier (16 co-resident CTAs, sense via generation counter) ----
        if (tid == 0) {
            unsigned target = (unsigned)(t + 1);
            if (atomicAdd(&d_bar_count[g], 1u) == CPG - 1) {
                d_bar_count[g] = 0;
                __threadfence();
                d_bar_gen[g] = target;
            } else {
                while (d_bar_gen[g] < target) { }
            }
            __threadfence();
        }
        __syncthreads();
    }
}

// ===================== launch =====================
extern "C" void kernel_launch(void* const* d_in, const int* in_sizes, int n_in,
                              void* d_out, int out_size) {
    const float* x  = (const float*)d_in[0];
    const float* ie = (const float*)d_in[1];
    const float* he = (const float*)d_in[2];
    const float* me = (const float*)d_in[3];
    const float* ik = (const float*)d_in[4];
    const float* hk = (const float*)d_in[5];
    const float* mk = (const float*)d_in[6];
    const float* AT = (const float*)d_in[7];
    const float* BT = (const float*)d_in[8];
    float* out = (float*)d_out;

    cudaFuncSetAttribute(lmu_main_kernel,
                         cudaFuncAttributeMaxDynamicSharedMemorySize, SMEM_BYTES);

    lmu_setup_kernel<<<520, 256>>>(mk, AT, BT);
    lmu_main_kernel<<<NCTA, NTHREADS, SMEM_BYTES>>>(x, ie, he, me, ik, hk, AT, BT, out);
}